// round 12
// baseline (speedup 1.0000x reference)
#include <cuda_runtime.h>
#include <cuda_bf16.h>
#include <cstdint>
#include <cstddef>

#define NNODES 100000
#define NLAST  (NNODES - 1)
#define NWORDS 3125            // ceil(100000/32)
#define CAP1   4096
#define CAP2   32768
#define GRID   148
#define TPB    1024
#define NTHREADS (GRID * TPB)

// ---- scratch (device globals; zero at load; cleaned at kernel end) --------
__device__ int           g_deg[NNODES];
__device__ float         g_s[NNODES];
__device__ int           g_s1[CAP1];
__device__ int2          g_pair[CAP2];
__device__ int           g_count1;
__device__ int           g_count2;
__device__ unsigned int           g_bar_count;
__device__ volatile unsigned int  g_bar_gen;
__device__ volatile unsigned int  g_done;

// ---- software grid barrier ------------------------------------------------
__device__ __forceinline__ void grid_barrier() {
    __syncthreads();
    if (threadIdx.x == 0) {
        __threadfence();
        unsigned gen = g_bar_gen;
        unsigned arrived = atomicAdd(&g_bar_count, 1u);
        if (arrived == GRID - 1) {
            g_bar_count = 0u;
            __threadfence();
            g_bar_gen = gen + 1u;
        } else {
            while (g_bar_gen == gen) { }
        }
        __threadfence();
    }
    __syncthreads();
}

#define BM_TEST(bm, v)  (((bm)[(v) >> 5] >> ((v) & 31)) & 1u)

// ---------------------------------------------------------------------------
// chunkN > 0  -> int32 fast path: block's dst chunk staged in dynamic smem.
// chunkN == 0 -> fallback: direct global scans (also used for int64 mode).
__global__ void __launch_bounds__(TPB, 1)
gcn_fused_kernel(const void* __restrict__ eidx,
                 const float* __restrict__ x,
                 const float* __restrict__ W1, const float* __restrict__ b1,
                 const float* __restrict__ W2, const float* __restrict__ b2,
                 const float* __restrict__ Wfc, const float* __restrict__ bfc,
                 float* __restrict__ out, int E, int chunkN) {
    const int tid = blockIdx.x * TPB + threadIdx.x;

    extern __shared__ unsigned char dynsmem[];
    int*          s_chunk = (int*)dynsmem;
    unsigned int* s_bm    = (unsigned int*)(dynsmem + (size_t)chunkN * 4);

    __shared__ int sh_mode;

    // per-block dtype detect (same 256B everywhere; L2 broadcast)
    if (threadIdx.x == 0) {
        const unsigned int* w = (const unsigned int*)eidx;
        int all0 = 1;
        #pragma unroll
        for (int i = 0; i < 32; i++)
            if (w[2 * i + 1] != 0u) all0 = 0;
        sh_mode = all0;
    }
    for (int wdx = threadIdx.x; wdx < NWORDS; wdx += TPB) s_bm[wdx] = 0u;
    __syncthreads();
    const int mode = sh_mode;

    const int* __restrict__ srcp32 = (const int*)eidx;
    const int* __restrict__ dstp32 = srcp32 + E;

    const bool fast = (!mode) && (chunkN > 0) &&
                      (((unsigned long long)(size_t)dstp32 & 15ull) == 0ull);

    const int base = blockIdx.x * chunkN;
    int myN = E - base; if (myN > chunkN) myN = chunkN; if (myN < 0) myN = 0;
    const int nv4 = myN >> 2;                    // myN is a multiple of 4
    const int4* __restrict__ gdv = (const int4*)(dstp32 + base);
    int4* sc4 = (int4*)s_chunk;

    // ================= P1: cp.async stage chunk + test dst == N-1 ==========
    if (fast) {
        // issue async copies (no register round-trip, deep HW queue)
        for (int j = threadIdx.x; j < nv4; j += TPB) {
            unsigned long long saddr = __cvta_generic_to_shared(sc4 + j);
            asm volatile("cp.async.cg.shared.global [%0], [%1], 16;"
                         :: "r"((unsigned int)saddr), "l"(gdv + j));
        }
        asm volatile("cp.async.commit_group;");

        // block 0 prefetches x into L2 for the P5/P6 tail (1 per 128B line)
        if (blockIdx.x == 0) {
            for (int i = threadIdx.x * 32; i < NNODES; i += TPB * 32)
                asm volatile("prefetch.global.L2 [%0];" :: "l"(x + i));
        }

        asm volatile("cp.async.wait_group 0;");
        __syncthreads();

        // scan smem for dst == N-1
        for (int j = threadIdx.x; j < nv4; j += TPB) {
            int4 d4 = sc4[j];
            int gi = base + 4 * j;
            if (d4.x == NLAST) { int p = atomicAdd(&g_count1, 1); if (p < CAP1) g_s1[p] = srcp32[gi + 0]; }
            if (d4.y == NLAST) { int p = atomicAdd(&g_count1, 1); if (p < CAP1) g_s1[p] = srcp32[gi + 1]; }
            if (d4.z == NLAST) { int p = atomicAdd(&g_count1, 1); if (p < CAP1) g_s1[p] = srcp32[gi + 2]; }
            if (d4.w == NLAST) { int p = atomicAdd(&g_count1, 1); if (p < CAP1) g_s1[p] = srcp32[gi + 3]; }
        }
    } else if (mode) {
        const long long* __restrict__ srcp = (const long long*)eidx;
        const long long* __restrict__ dstp = srcp + E;
        for (int e = tid; e < E; e += NTHREADS) {
            if ((int)dstp[e] == NLAST) { int p = atomicAdd(&g_count1, 1); if (p < CAP1) g_s1[p] = (int)srcp[e]; }
        }
    } else {
        for (int e = tid; e < E; e += NTHREADS) {
            if (dstp32[e] == NLAST) { int p = atomicAdd(&g_count1, 1); if (p < CAP1) g_s1[p] = srcp32[e]; }
        }
    }
    grid_barrier();   // barrier #1

    // build needed bitmask per-block in smem from g_s1
    {
        int c1 = g_count1; if (c1 > CAP1) c1 = CAP1;
        for (int k = threadIdx.x; k < c1; k += TPB) {
            int u = g_s1[k];
            atomicOr(&s_bm[u >> 5], 1u << (u & 31));
        }
        if (threadIdx.x == 0) atomicOr(&s_bm[NLAST >> 5], 1u << (NLAST & 31));
    }
    __syncthreads();

    // ================= P3: scan (smem) — edges into needed set =============
    if (fast) {
        for (int j = threadIdx.x; j < nv4; j += TPB) {
            int4 d4 = sc4[j];
            int gi = base + 4 * j;
            if (BM_TEST(s_bm, d4.x)) { int p = atomicAdd(&g_count2, 1); if (p < CAP2) g_pair[p] = make_int2(srcp32[gi + 0], d4.x); }
            if (BM_TEST(s_bm, d4.y)) { int p = atomicAdd(&g_count2, 1); if (p < CAP2) g_pair[p] = make_int2(srcp32[gi + 1], d4.y); }
            if (BM_TEST(s_bm, d4.z)) { int p = atomicAdd(&g_count2, 1); if (p < CAP2) g_pair[p] = make_int2(srcp32[gi + 2], d4.z); }
            if (BM_TEST(s_bm, d4.w)) { int p = atomicAdd(&g_count2, 1); if (p < CAP2) g_pair[p] = make_int2(srcp32[gi + 3], d4.w); }
        }
    } else if (mode) {
        const long long* __restrict__ srcp = (const long long*)eidx;
        const long long* __restrict__ dstp = srcp + E;
        for (int e = tid; e < E; e += NTHREADS) {
            int d = (int)dstp[e];
            if (BM_TEST(s_bm, d)) { int p = atomicAdd(&g_count2, 1); if (p < CAP2) g_pair[p] = make_int2((int)srcp[e], d); }
        }
    } else {
        for (int e = tid; e < E; e += NTHREADS) {
            int d = dstp32[e];
            if (BM_TEST(s_bm, d)) { int p = atomicAdd(&g_count2, 1); if (p < CAP2) g_pair[p] = make_int2(srcp32[e], d); }
        }
    }
    grid_barrier();   // barrier #2

    // extend bitmask with pair srcs -> need_deg set
    {
        int c2 = g_count2; if (c2 > CAP2) c2 = CAP2;
        for (int k = threadIdx.x; k < c2; k += TPB) {
            int u = g_pair[k].x;
            atomicOr(&s_bm[u >> 5], 1u << (u & 31));
        }
    }
    __syncthreads();

    // ================= P4: filtered degree scan (smem) =====================
    if (fast) {
        for (int j = threadIdx.x; j < nv4; j += TPB) {
            int4 d4 = sc4[j];
            if (BM_TEST(s_bm, d4.x)) atomicAdd(&g_deg[d4.x], 1);
            if (BM_TEST(s_bm, d4.y)) atomicAdd(&g_deg[d4.y], 1);
            if (BM_TEST(s_bm, d4.z)) atomicAdd(&g_deg[d4.z], 1);
            if (BM_TEST(s_bm, d4.w)) atomicAdd(&g_deg[d4.w], 1);
        }
    } else if (mode) {
        const long long* __restrict__ dstp = (const long long*)eidx + E;
        for (int e = tid; e < E; e += NTHREADS) {
            int d = (int)dstp[e];
            if (BM_TEST(s_bm, d)) atomicAdd(&g_deg[d], 1);
        }
    } else {
        for (int e = tid; e < E; e += NTHREADS) {
            int d = dstp32[e];
            if (BM_TEST(s_bm, d)) atomicAdd(&g_deg[d], 1);
        }
    }

    // ---- final sync: done-counter; non-zero blocks arrive and EXIT --------
    __syncthreads();
    if (blockIdx.x != 0) {
        if (threadIdx.x == 0) {
            __threadfence();
            atomicAdd((unsigned int*)&g_done, 1u);
        }
        return;
    }
    if (threadIdx.x == 0) {
        __threadfence();
        while (g_done < GRID - 1) { }
        __threadfence();
    }
    __syncthreads();

    // ================= P5+P6+cleanup: block 0 only =========================
    {
        int c1 = g_count1; if (c1 > CAP1) c1 = CAP1;
        int c2 = g_count2; if (c2 > CAP2) c2 = CAP2;

        // P5: layer-1 aggregation over pairs (x now L2-warm)
        for (int k = threadIdx.x; k < c2; k += TPB) {
            int2 pr = g_pair[k];
            float dis = rsqrtf((float)(__ldcg(&g_deg[pr.x]) + 1));
            float did = rsqrtf((float)(__ldcg(&g_deg[pr.y]) + 1));
            atomicAdd(&g_s[pr.y], x[pr.x] * dis * did);
        }
        __syncthreads();
        __threadfence();

        // P6: layer-2 @ node N-1 + fc head (warp 0)
        if (threadIdx.x < 32) {
            int lane = threadIdx.x;
            __shared__ float sW1[16], sb1[16], sW2[128], sb2[8], sWfc[8];
            if (lane < 16) { sW1[lane] = W1[lane]; sb1[lane] = b1[lane]; }
            if (lane < 8)  { sb2[lane] = b2[lane]; sWfc[lane] = Wfc[lane]; }
            for (int k = lane; k < 128; k += 32) sW2[k] = W2[k];
            __syncwarp();

            const float dinvL = rsqrtf((float)(__ldcg(&g_deg[NLAST]) + 1));

            float agg[8];
            #pragma unroll
            for (int j = 0; j < 8; j++) agg[j] = 0.0f;

            // k in [0, c1): real edges into N-1; k == c1: appended self-loop.
            for (int k = lane; k <= c1; k += 32) {
                int u = (k == c1) ? NLAST : g_s1[k];
                float du = rsqrtf((float)(__ldcg(&g_deg[u]) + 1));
                float norm = du * dinvL;
                float su = __ldcg(&g_s[u]) + x[u] * du * du;
                float h1[16];
                #pragma unroll
                for (int j = 0; j < 16; j++)
                    h1[j] = fmaxf(fmaf(su, sW1[j], sb1[j]), 0.0f);
                #pragma unroll
                for (int j = 0; j < 8; j++) {
                    float v = 0.0f;
                    #pragma unroll
                    for (int t = 0; t < 16; t++) v = fmaf(h1[t], sW2[t * 8 + j], v);
                    agg[j] = fmaf(v, norm, agg[j]);
                }
            }
            #pragma unroll
            for (int off = 16; off > 0; off >>= 1) {
                #pragma unroll
                for (int j = 0; j < 8; j++)
                    agg[j] += __shfl_down_sync(0xffffffff, agg[j], off);
            }
            if (lane == 0) {
                float o = bfc[0];
                #pragma unroll
                for (int j = 0; j < 8; j++) {
                    float h2 = fmaxf(agg[j] + sb2[j], 0.0f);
                    o = fmaf(h2, sWfc[j], o);
                }
                out[0] = o;
            }
        }
        __syncthreads();

        // cleanup: zero all touched scratch for the next replay
        for (int k = threadIdx.x; k < c1; k += TPB) {
            int u = g_s1[k];
            g_deg[u] = 0; g_s[u] = 0.0f;
        }
        for (int k = threadIdx.x; k < c2; k += TPB) {
            int2 pr = g_pair[k];
            g_deg[pr.x] = 0; g_s[pr.x] = 0.0f;
            g_deg[pr.y] = 0; g_s[pr.y] = 0.0f;
        }
        if (threadIdx.x == 0) {
            g_deg[NLAST] = 0; g_s[NLAST] = 0.0f;
            g_count1 = 0; g_count2 = 0;
            g_done = 0u;
        }
    }
}

// ---------------------------------------------------------------------------
extern "C" void kernel_launch(void* const* d_in, const int* in_sizes, int n_in,
                              void* d_out, int out_size) {
    const float* x    = (const float*)d_in[0];
    const void*  eidx = d_in[1];
    const float* W1   = (const float*)d_in[2];
    const float* b1   = (const float*)d_in[3];
    const float* W2   = (const float*)d_in[4];
    const float* b2   = (const float*)d_in[5];
    const float* Wfc  = (const float*)d_in[6];
    const float* bfc  = (const float*)d_in[7];
    float* out = (float*)d_out;

    int E = in_sizes[1] / 2;

    // per-block contiguous dst chunk, staged in dynamic smem
    int chunkN = (((E + GRID - 1) / GRID) + 3) & ~3;
    size_t smem = (size_t)chunkN * 4 + (size_t)NWORDS * 4 + 16;
    bool ok = (E % 4 == 0) && (smem <= 200 * 1024);
    if (!ok) {
        chunkN = 0;
        smem = (size_t)NWORDS * 4 + 16;
    }
    cudaFuncSetAttribute(gcn_fused_kernel,
                         cudaFuncAttributeMaxDynamicSharedMemorySize, (int)smem);

    gcn_fused_kernel<<<GRID, TPB, smem>>>(eidx, x, W1, b1, W2, b2, Wfc, bfc,
                                          out, E, chunkN);
}

// round 13
// speedup vs baseline: 1.0659x; 1.0659x over previous
#include <cuda_runtime.h>
#include <cuda_bf16.h>
#include <cstdint>
#include <cstddef>

#define NNODES 100000
#define NLAST  (NNODES - 1)
#define NWORDS 3125            // ceil(100000/32)
#define CAP1   4096
#define CAP2   32768
#define GRID   148
#define TPB    1024
#define NTHREADS (GRID * TPB)

// ---- scratch (device globals; zero at load; cleaned at kernel end) --------
__device__ int           g_deg[NNODES];
__device__ float         g_s[NNODES];
__device__ int           g_s1[CAP1];
__device__ int2          g_pair[CAP2];
__device__ int           g_count1;
__device__ int           g_count2;
__device__ unsigned int  g_cnt[3];     // per-barrier arrival counters

// ---- fire-and-forget grid barrier: REDG arrive + direct counter poll ------
__device__ __forceinline__ void barrier_arrive_wait(int idx) {
    __syncthreads();
    if (threadIdx.x == 0) {
        __threadfence();
        asm volatile("red.relaxed.gpu.global.add.u32 [%0], 1;"
                     :: "l"(g_cnt + idx) : "memory");
        while (((volatile unsigned int*)g_cnt)[idx] < GRID) { }
        __threadfence();
    }
    __syncthreads();
}

#define BM_TEST(bm, v)  (((bm)[(v) >> 5] >> ((v) & 31)) & 1u)

// ---------------------------------------------------------------------------
// chunkN > 0  -> int32 fast path: block's dst chunk staged in dynamic smem.
// chunkN == 0 -> fallback: direct global scans (also used for int64 mode).
__global__ void __launch_bounds__(TPB, 1)
gcn_fused_kernel(const void* __restrict__ eidx,
                 const float* __restrict__ x,
                 const float* __restrict__ W1, const float* __restrict__ b1,
                 const float* __restrict__ W2, const float* __restrict__ b2,
                 const float* __restrict__ Wfc, const float* __restrict__ bfc,
                 float* __restrict__ out, int E, int chunkN) {
    const int tid = blockIdx.x * TPB + threadIdx.x;

    extern __shared__ unsigned char dynsmem[];
    int*          s_chunk = (int*)dynsmem;
    unsigned int* s_bm    = (unsigned int*)(dynsmem + (size_t)chunkN * 4);

    __shared__ int sh_mode;

    // per-block dtype detect (same 256B everywhere; L2 broadcast)
    if (threadIdx.x == 0) {
        const unsigned int* w = (const unsigned int*)eidx;
        int all0 = 1;
        #pragma unroll
        for (int i = 0; i < 32; i++)
            if (w[2 * i + 1] != 0u) all0 = 0;
        sh_mode = all0;
    }
    for (int wdx = threadIdx.x; wdx < NWORDS; wdx += TPB) s_bm[wdx] = 0u;
    __syncthreads();
    const int mode = sh_mode;

    const int* __restrict__ srcp32 = (const int*)eidx;
    const int* __restrict__ dstp32 = srcp32 + E;

    const bool fast = (!mode) && (chunkN > 0) &&
                      (((unsigned long long)(size_t)dstp32 & 15ull) == 0ull);

    const int base = blockIdx.x * chunkN;
    int myN = E - base; if (myN > chunkN) myN = chunkN; if (myN < 0) myN = 0;
    const int nv4 = myN >> 2;                    // myN is a multiple of 4
    const int4* __restrict__ gdv = (const int4*)(dstp32 + base);
    int4* sc4 = (int4*)s_chunk;

    // ================= P1: stage chunk via registers + test dst == N-1 =====
    if (fast) {
        int4 v[6]; int ii[6];
        #pragma unroll
        for (int k = 0; k < 6; k++) {
            ii[k] = threadIdx.x + k * TPB;
            if (ii[k] < nv4) v[k] = gdv[ii[k]];
        }
        // block 0 prefetches x into L2 for the P5/P6 tail (1 per 128B line)
        if (blockIdx.x == 0) {
            for (int i = threadIdx.x * 32; i < NNODES; i += TPB * 32)
                asm volatile("prefetch.global.L2 [%0];" :: "l"(x + i));
        }
        #pragma unroll
        for (int k = 0; k < 6; k++) {
            if (ii[k] < nv4) {
                sc4[ii[k]] = v[k];
                int gi = base + 4 * ii[k];
                if (v[k].x == NLAST) { int p = atomicAdd(&g_count1, 1); if (p < CAP1) g_s1[p] = srcp32[gi + 0]; }
                if (v[k].y == NLAST) { int p = atomicAdd(&g_count1, 1); if (p < CAP1) g_s1[p] = srcp32[gi + 1]; }
                if (v[k].z == NLAST) { int p = atomicAdd(&g_count1, 1); if (p < CAP1) g_s1[p] = srcp32[gi + 2]; }
                if (v[k].w == NLAST) { int p = atomicAdd(&g_count1, 1); if (p < CAP1) g_s1[p] = srcp32[gi + 3]; }
            }
        }
    } else if (mode) {
        const long long* __restrict__ srcp = (const long long*)eidx;
        const long long* __restrict__ dstp = srcp + E;
        for (int e = tid; e < E; e += NTHREADS) {
            if ((int)dstp[e] == NLAST) { int p = atomicAdd(&g_count1, 1); if (p < CAP1) g_s1[p] = (int)srcp[e]; }
        }
    } else {
        for (int e = tid; e < E; e += NTHREADS) {
            if (dstp32[e] == NLAST) { int p = atomicAdd(&g_count1, 1); if (p < CAP1) g_s1[p] = srcp32[e]; }
        }
    }
    barrier_arrive_wait(0);   // barrier #1

    // build needed bitmask per-block in smem from g_s1
    {
        int c1 = g_count1; if (c1 > CAP1) c1 = CAP1;
        for (int k = threadIdx.x; k < c1; k += TPB) {
            int u = g_s1[k];
            atomicOr(&s_bm[u >> 5], 1u << (u & 31));
        }
        if (threadIdx.x == 0) atomicOr(&s_bm[NLAST >> 5], 1u << (NLAST & 31));
    }
    __syncthreads();

    // ================= P3: scan (smem) — edges into needed set =============
    if (fast) {
        for (int j = threadIdx.x; j < nv4; j += TPB) {
            int4 d4 = sc4[j];
            int gi = base + 4 * j;
            if (BM_TEST(s_bm, d4.x)) { int p = atomicAdd(&g_count2, 1); if (p < CAP2) g_pair[p] = make_int2(srcp32[gi + 0], d4.x); }
            if (BM_TEST(s_bm, d4.y)) { int p = atomicAdd(&g_count2, 1); if (p < CAP2) g_pair[p] = make_int2(srcp32[gi + 1], d4.y); }
            if (BM_TEST(s_bm, d4.z)) { int p = atomicAdd(&g_count2, 1); if (p < CAP2) g_pair[p] = make_int2(srcp32[gi + 2], d4.z); }
            if (BM_TEST(s_bm, d4.w)) { int p = atomicAdd(&g_count2, 1); if (p < CAP2) g_pair[p] = make_int2(srcp32[gi + 3], d4.w); }
        }
    } else if (mode) {
        const long long* __restrict__ srcp = (const long long*)eidx;
        const long long* __restrict__ dstp = srcp + E;
        for (int e = tid; e < E; e += NTHREADS) {
            int d = (int)dstp[e];
            if (BM_TEST(s_bm, d)) { int p = atomicAdd(&g_count2, 1); if (p < CAP2) g_pair[p] = make_int2((int)srcp[e], d); }
        }
    } else {
        for (int e = tid; e < E; e += NTHREADS) {
            int d = dstp32[e];
            if (BM_TEST(s_bm, d)) { int p = atomicAdd(&g_count2, 1); if (p < CAP2) g_pair[p] = make_int2(srcp32[e], d); }
        }
    }
    barrier_arrive_wait(1);   // barrier #2

    // extend bitmask with pair srcs -> need_deg set
    {
        int c2 = g_count2; if (c2 > CAP2) c2 = CAP2;
        for (int k = threadIdx.x; k < c2; k += TPB) {
            int u = g_pair[k].x;
            atomicOr(&s_bm[u >> 5], 1u << (u & 31));
        }
    }
    __syncthreads();

    // ================= P4: filtered degree scan (smem) =====================
    if (fast) {
        for (int j = threadIdx.x; j < nv4; j += TPB) {
            int4 d4 = sc4[j];
            if (BM_TEST(s_bm, d4.x)) atomicAdd(&g_deg[d4.x], 1);
            if (BM_TEST(s_bm, d4.y)) atomicAdd(&g_deg[d4.y], 1);
            if (BM_TEST(s_bm, d4.z)) atomicAdd(&g_deg[d4.z], 1);
            if (BM_TEST(s_bm, d4.w)) atomicAdd(&g_deg[d4.w], 1);
        }
    } else if (mode) {
        const long long* __restrict__ dstp = (const long long*)eidx + E;
        for (int e = tid; e < E; e += NTHREADS) {
            int d = (int)dstp[e];
            if (BM_TEST(s_bm, d)) atomicAdd(&g_deg[d], 1);
        }
    } else {
        for (int e = tid; e < E; e += NTHREADS) {
            int d = dstp32[e];
            if (BM_TEST(s_bm, d)) atomicAdd(&g_deg[d], 1);
        }
    }

    // ---- final sync: fire-and-forget arrive; non-zero blocks EXIT ---------
    __syncthreads();
    if (threadIdx.x == 0) {
        __threadfence();
        asm volatile("red.relaxed.gpu.global.add.u32 [%0], 1;"
                     :: "l"(g_cnt + 2) : "memory");
    }
    if (blockIdx.x != 0) return;
    if (threadIdx.x == 0) {
        while (((volatile unsigned int*)g_cnt)[2] < GRID) { }
        __threadfence();
    }
    __syncthreads();

    // ================= P5+P6+cleanup: block 0 only =========================
    {
        int c1 = g_count1; if (c1 > CAP1) c1 = CAP1;
        int c2 = g_count2; if (c2 > CAP2) c2 = CAP2;

        // P5: layer-1 aggregation over pairs (x is L2-warm from prefetch)
        for (int k = threadIdx.x; k < c2; k += TPB) {
            int2 pr = g_pair[k];
            float dis = rsqrtf((float)(__ldcg(&g_deg[pr.x]) + 1));
            float did = rsqrtf((float)(__ldcg(&g_deg[pr.y]) + 1));
            atomicAdd(&g_s[pr.y], x[pr.x] * dis * did);
        }
        __syncthreads();
        __threadfence();

        // P6: layer-2 @ node N-1 + fc head (warp 0)
        if (threadIdx.x < 32) {
            int lane = threadIdx.x;
            __shared__ float sW1[16], sb1[16], sW2[128], sb2[8], sWfc[8];
            if (lane < 16) { sW1[lane] = W1[lane]; sb1[lane] = b1[lane]; }
            if (lane < 8)  { sb2[lane] = b2[lane]; sWfc[lane] = Wfc[lane]; }
            for (int k = lane; k < 128; k += 32) sW2[k] = W2[k];
            __syncwarp();

            const float dinvL = rsqrtf((float)(__ldcg(&g_deg[NLAST]) + 1));

            float agg[8];
            #pragma unroll
            for (int j = 0; j < 8; j++) agg[j] = 0.0f;

            // k in [0, c1): real edges into N-1; k == c1: appended self-loop.
            for (int k = lane; k <= c1; k += 32) {
                int u = (k == c1) ? NLAST : g_s1[k];
                float du = rsqrtf((float)(__ldcg(&g_deg[u]) + 1));
                float norm = du * dinvL;
                float su = __ldcg(&g_s[u]) + x[u] * du * du;
                float h1[16];
                #pragma unroll
                for (int j = 0; j < 16; j++)
                    h1[j] = fmaxf(fmaf(su, sW1[j], sb1[j]), 0.0f);
                #pragma unroll
                for (int j = 0; j < 8; j++) {
                    float v = 0.0f;
                    #pragma unroll
                    for (int t = 0; t < 16; t++) v = fmaf(h1[t], sW2[t * 8 + j], v);
                    agg[j] = fmaf(v, norm, agg[j]);
                }
            }
            #pragma unroll
            for (int off = 16; off > 0; off >>= 1) {
                #pragma unroll
                for (int j = 0; j < 8; j++)
                    agg[j] += __shfl_down_sync(0xffffffff, agg[j], off);
            }
            if (lane == 0) {
                float o = bfc[0];
                #pragma unroll
                for (int j = 0; j < 8; j++) {
                    float h2 = fmaxf(agg[j] + sb2[j], 0.0f);
                    o = fmaf(h2, sWfc[j], o);
                }
                out[0] = o;
            }
        }
        __syncthreads();

        // cleanup: zero all touched scratch for the next replay
        for (int k = threadIdx.x; k < c1; k += TPB) {
            int u = g_s1[k];
            g_deg[u] = 0; g_s[u] = 0.0f;
        }
        for (int k = threadIdx.x; k < c2; k += TPB) {
            int2 pr = g_pair[k];
            g_deg[pr.x] = 0; g_s[pr.x] = 0.0f;
            g_deg[pr.y] = 0; g_s[pr.y] = 0.0f;
        }
        if (threadIdx.x == 0) {
            g_deg[NLAST] = 0; g_s[NLAST] = 0.0f;
            g_count1 = 0; g_count2 = 0;
            g_cnt[0] = 0u; g_cnt[1] = 0u; g_cnt[2] = 0u;
        }
    }
}

// ---------------------------------------------------------------------------
extern "C" void kernel_launch(void* const* d_in, const int* in_sizes, int n_in,
                              void* d_out, int out_size) {
    const float* x    = (const float*)d_in[0];
    const void*  eidx = d_in[1];
    const float* W1   = (const float*)d_in[2];
    const float* b1   = (const float*)d_in[3];
    const float* W2   = (const float*)d_in[4];
    const float* b2   = (const float*)d_in[5];
    const float* Wfc  = (const float*)d_in[6];
    const float* bfc  = (const float*)d_in[7];
    float* out = (float*)d_out;

    int E = in_sizes[1] / 2;

    // per-block contiguous dst chunk, staged in dynamic smem
    int chunkN = (((E + GRID - 1) / GRID) + 3) & ~3;
    size_t smem = (size_t)chunkN * 4 + (size_t)NWORDS * 4 + 16;
    bool ok = (E % 4 == 0) && ((chunkN >> 2) <= 6 * TPB) && (smem <= 200 * 1024);
    if (!ok) {
        chunkN = 0;
        smem = (size_t)NWORDS * 4 + 16;
    }
    cudaFuncSetAttribute(gcn_fused_kernel,
                         cudaFuncAttributeMaxDynamicSharedMemorySize, (int)smem);

    gcn_fused_kernel<<<GRID, TPB, smem>>>(eidx, x, W1, b1, W2, b2, Wfc, bfc,
                                          out, E, chunkN);
}

// round 14
// speedup vs baseline: 1.1225x; 1.0532x over previous
#include <cuda_runtime.h>
#include <cuda_bf16.h>
#include <cstdint>
#include <cstddef>

#define NNODES 100000
#define NLAST  (NNODES - 1)
#define NWORDS 3125            // ceil(100000/32)
#define CAP1   4096
#define CAP2   32768
#define GRID   148
#define TPB    1024
#define NTHREADS (GRID * TPB)

// ---- scratch (device globals; zero at load; cleaned at kernel end) --------
__device__ int           g_deg[NNODES];
__device__ float         g_s[NNODES];
__device__ int           g_s1[CAP1];
__device__ int2          g_pair[CAP2];
__device__ int           g_count1;
__device__ int           g_count2;
__device__ unsigned int  g_cnt[3];     // per-barrier arrival counters

// ---- fire-and-forget grid barrier: REDG arrive + direct counter poll ------
__device__ __forceinline__ void barrier_arrive_wait(int idx) {
    __syncthreads();
    if (threadIdx.x == 0) {
        __threadfence();
        asm volatile("red.relaxed.gpu.global.add.u32 [%0], 1;"
                     :: "l"(g_cnt + idx) : "memory");
        while (((volatile unsigned int*)g_cnt)[idx] < GRID) { }
        __threadfence();
    }
    __syncthreads();
}

#define BM_TEST(bm, v)  (((bm)[(v) >> 5] >> ((v) & 31)) & 1u)

// ---------------------------------------------------------------------------
__global__ void __launch_bounds__(TPB, 1)
gcn_fused_kernel(const void* __restrict__ eidx,
                 const float* __restrict__ x,
                 const float* __restrict__ W1, const float* __restrict__ b1,
                 const float* __restrict__ W2, const float* __restrict__ b2,
                 const float* __restrict__ Wfc, const float* __restrict__ bfc,
                 float* __restrict__ out, int E, int chunkN) {
    const int tid = blockIdx.x * TPB + threadIdx.x;

    extern __shared__ unsigned char dynsmem[];
    int*          s_chunk = (int*)dynsmem;
    unsigned int* s_bm    = (unsigned int*)(dynsmem + (size_t)chunkN * 4);

    __shared__ int sh_mode;
    __shared__ int sh_last;

    // per-block dtype detect (same 256B everywhere; L2 broadcast)
    if (threadIdx.x == 0) {
        const unsigned int* w = (const unsigned int*)eidx;
        int all0 = 1;
        #pragma unroll
        for (int i = 0; i < 32; i++)
            if (w[2 * i + 1] != 0u) all0 = 0;
        sh_mode = all0;
        sh_last = 0;
    }
    for (int wdx = threadIdx.x; wdx < NWORDS; wdx += TPB) s_bm[wdx] = 0u;
    __syncthreads();
    const int mode = sh_mode;

    const int* __restrict__ srcp32 = (const int*)eidx;
    const int* __restrict__ dstp32 = srcp32 + E;

    const bool fast = (!mode) && (chunkN > 0) &&
                      (((unsigned long long)(size_t)dstp32 & 15ull) == 0ull);

    const int base = blockIdx.x * chunkN;
    int myN = E - base; if (myN > chunkN) myN = chunkN; if (myN < 0) myN = 0;
    const int nv4 = myN >> 2;                    // myN is a multiple of 4
    const int4* __restrict__ gdv = (const int4*)(dstp32 + base);
    int4* sc4 = (int4*)s_chunk;

    // ================= P1: stage chunk via registers + test dst == N-1 =====
    if (fast) {
        int4 v[6]; int ii[6];
        #pragma unroll
        for (int k = 0; k < 6; k++) {
            ii[k] = threadIdx.x + k * TPB;
            if (ii[k] < nv4) v[k] = gdv[ii[k]];
        }
        // all blocks prefetch a disjoint slice of x into L2 for the tail
        {
            int lines = (NNODES + 31) / 32;                 // 128B lines
            int per_blk = (lines + GRID - 1) / GRID;
            int l0 = blockIdx.x * per_blk;
            for (int l = l0 + threadIdx.x; l < l0 + per_blk && l < lines; l += TPB)
                asm volatile("prefetch.global.L2 [%0];" :: "l"(x + l * 32));
        }
        #pragma unroll
        for (int k = 0; k < 6; k++) {
            if (ii[k] < nv4) {
                sc4[ii[k]] = v[k];
                int gi = base + 4 * ii[k];
                if (v[k].x == NLAST) { int p = atomicAdd(&g_count1, 1); if (p < CAP1) g_s1[p] = srcp32[gi + 0]; }
                if (v[k].y == NLAST) { int p = atomicAdd(&g_count1, 1); if (p < CAP1) g_s1[p] = srcp32[gi + 1]; }
                if (v[k].z == NLAST) { int p = atomicAdd(&g_count1, 1); if (p < CAP1) g_s1[p] = srcp32[gi + 2]; }
                if (v[k].w == NLAST) { int p = atomicAdd(&g_count1, 1); if (p < CAP1) g_s1[p] = srcp32[gi + 3]; }
            }
        }
    } else if (mode) {
        const long long* __restrict__ srcp = (const long long*)eidx;
        const long long* __restrict__ dstp = srcp + E;
        for (int e = tid; e < E; e += NTHREADS) {
            if ((int)dstp[e] == NLAST) { int p = atomicAdd(&g_count1, 1); if (p < CAP1) g_s1[p] = (int)srcp[e]; }
        }
    } else {
        for (int e = tid; e < E; e += NTHREADS) {
            if (dstp32[e] == NLAST) { int p = atomicAdd(&g_count1, 1); if (p < CAP1) g_s1[p] = srcp32[e]; }
        }
    }
    barrier_arrive_wait(0);   // barrier #1

    // build needed bitmask per-block in smem from g_s1
    {
        int c1 = g_count1; if (c1 > CAP1) c1 = CAP1;
        for (int k = threadIdx.x; k < c1; k += TPB) {
            int u = g_s1[k];
            atomicOr(&s_bm[u >> 5], 1u << (u & 31));
        }
        if (threadIdx.x == 0) atomicOr(&s_bm[NLAST >> 5], 1u << (NLAST & 31));
    }
    __syncthreads();

    // ================= P3: scan (smem) — edges into needed set =============
    if (fast) {
        for (int j = threadIdx.x; j < nv4; j += TPB) {
            int4 d4 = sc4[j];
            int gi = base + 4 * j;
            if (BM_TEST(s_bm, d4.x)) { int p = atomicAdd(&g_count2, 1); if (p < CAP2) g_pair[p] = make_int2(srcp32[gi + 0], d4.x); }
            if (BM_TEST(s_bm, d4.y)) { int p = atomicAdd(&g_count2, 1); if (p < CAP2) g_pair[p] = make_int2(srcp32[gi + 1], d4.y); }
            if (BM_TEST(s_bm, d4.z)) { int p = atomicAdd(&g_count2, 1); if (p < CAP2) g_pair[p] = make_int2(srcp32[gi + 2], d4.z); }
            if (BM_TEST(s_bm, d4.w)) { int p = atomicAdd(&g_count2, 1); if (p < CAP2) g_pair[p] = make_int2(srcp32[gi + 3], d4.w); }
        }
    } else if (mode) {
        const long long* __restrict__ srcp = (const long long*)eidx;
        const long long* __restrict__ dstp = srcp + E;
        for (int e = tid; e < E; e += NTHREADS) {
            int d = (int)dstp[e];
            if (BM_TEST(s_bm, d)) { int p = atomicAdd(&g_count2, 1); if (p < CAP2) g_pair[p] = make_int2((int)srcp[e], d); }
        }
    } else {
        for (int e = tid; e < E; e += NTHREADS) {
            int d = dstp32[e];
            if (BM_TEST(s_bm, d)) { int p = atomicAdd(&g_count2, 1); if (p < CAP2) g_pair[p] = make_int2(srcp32[e], d); }
        }
    }
    barrier_arrive_wait(1);   // barrier #2

    // extend bitmask with pair srcs -> need_deg set
    {
        int c2 = g_count2; if (c2 > CAP2) c2 = CAP2;
        for (int k = threadIdx.x; k < c2; k += TPB) {
            int u = g_pair[k].x;
            atomicOr(&s_bm[u >> 5], 1u << (u & 31));
        }
    }
    __syncthreads();

    // ================= P4: filtered degree scan (smem) =====================
    if (fast) {
        for (int j = threadIdx.x; j < nv4; j += TPB) {
            int4 d4 = sc4[j];
            if (BM_TEST(s_bm, d4.x)) atomicAdd(&g_deg[d4.x], 1);
            if (BM_TEST(s_bm, d4.y)) atomicAdd(&g_deg[d4.y], 1);
            if (BM_TEST(s_bm, d4.z)) atomicAdd(&g_deg[d4.z], 1);
            if (BM_TEST(s_bm, d4.w)) atomicAdd(&g_deg[d4.w], 1);
        }
    } else if (mode) {
        const long long* __restrict__ dstp = (const long long*)eidx + E;
        for (int e = tid; e < E; e += NTHREADS) {
            int d = (int)dstp[e];
            if (BM_TEST(s_bm, d)) atomicAdd(&g_deg[d], 1);
        }
    } else {
        for (int e = tid; e < E; e += NTHREADS) {
            int d = dstp32[e];
            if (BM_TEST(s_bm, d)) atomicAdd(&g_deg[d], 1);
        }
    }

    // ---- final sync: elect the LAST arriving block to run the tail --------
    __syncthreads();
    if (threadIdx.x == 0) {
        __threadfence();
        unsigned p = atomicAdd(&g_cnt[2], 1u);
        sh_last = (p == GRID - 1);
        if (sh_last) __threadfence();   // acquire all blocks' writes
    }
    __syncthreads();
    if (!sh_last) return;

    // ================= P5+P6+cleanup: last-arriving block only =============
    {
        int c1 = g_count1; if (c1 > CAP1) c1 = CAP1;
        int c2 = g_count2; if (c2 > CAP2) c2 = CAP2;

        // P5: layer-1 aggregation over pairs (x is L2-warm from prefetch)
        for (int k = threadIdx.x; k < c2; k += TPB) {
            int2 pr = g_pair[k];
            float dis = rsqrtf((float)(__ldcg(&g_deg[pr.x]) + 1));
            float did = rsqrtf((float)(__ldcg(&g_deg[pr.y]) + 1));
            atomicAdd(&g_s[pr.y], x[pr.x] * dis * did);
        }
        __syncthreads();
        __threadfence();

        // P6: layer-2 @ node N-1 + fc head (warp 0)
        if (threadIdx.x < 32) {
            int lane = threadIdx.x;
            __shared__ float sW1[16], sb1[16], sW2[128], sb2[8], sWfc[8];
            if (lane < 16) { sW1[lane] = W1[lane]; sb1[lane] = b1[lane]; }
            if (lane < 8)  { sb2[lane] = b2[lane]; sWfc[lane] = Wfc[lane]; }
            for (int k = lane; k < 128; k += 32) sW2[k] = W2[k];
            __syncwarp();

            const float dinvL = rsqrtf((float)(__ldcg(&g_deg[NLAST]) + 1));

            float agg[8];
            #pragma unroll
            for (int j = 0; j < 8; j++) agg[j] = 0.0f;

            // k in [0, c1): real edges into N-1; k == c1: appended self-loop.
            for (int k = lane; k <= c1; k += 32) {
                int u = (k == c1) ? NLAST : g_s1[k];
                float du = rsqrtf((float)(__ldcg(&g_deg[u]) + 1));
                float norm = du * dinvL;
                float su = __ldcg(&g_s[u]) + x[u] * du * du;
                float h1[16];
                #pragma unroll
                for (int j = 0; j < 16; j++)
                    h1[j] = fmaxf(fmaf(su, sW1[j], sb1[j]), 0.0f);
                #pragma unroll
                for (int j = 0; j < 8; j++) {
                    float v = 0.0f;
                    #pragma unroll
                    for (int t = 0; t < 16; t++) v = fmaf(h1[t], sW2[t * 8 + j], v);
                    agg[j] = fmaf(v, norm, agg[j]);
                }
            }
            #pragma unroll
            for (int off = 16; off > 0; off >>= 1) {
                #pragma unroll
                for (int j = 0; j < 8; j++)
                    agg[j] += __shfl_down_sync(0xffffffff, agg[j], off);
            }
            if (lane == 0) {
                float o = bfc[0];
                #pragma unroll
                for (int j = 0; j < 8; j++) {
                    float h2 = fmaxf(agg[j] + sb2[j], 0.0f);
                    o = fmaf(h2, sWfc[j], o);
                }
                out[0] = o;
            }
        }
        __syncthreads();

        // cleanup: zero all touched scratch for the next replay
        for (int k = threadIdx.x; k < c1; k += TPB) {
            int u = g_s1[k];
            g_deg[u] = 0; g_s[u] = 0.0f;
        }
        for (int k = threadIdx.x; k < c2; k += TPB) {
            int2 pr = g_pair[k];
            g_deg[pr.x] = 0; g_s[pr.x] = 0.0f;
            g_deg[pr.y] = 0; g_s[pr.y] = 0.0f;
        }
        if (threadIdx.x == 0) {
            g_deg[NLAST] = 0; g_s[NLAST] = 0.0f;
            g_count1 = 0; g_count2 = 0;
            g_cnt[0] = 0u; g_cnt[1] = 0u; g_cnt[2] = 0u;
        }
    }
}

// ---------------------------------------------------------------------------
extern "C" void kernel_launch(void* const* d_in, const int* in_sizes, int n_in,
                              void* d_out, int out_size) {
    const float* x    = (const float*)d_in[0];
    const void*  eidx = d_in[1];
    const float* W1   = (const float*)d_in[2];
    const float* b1   = (const float*)d_in[3];
    const float* W2   = (const float*)d_in[4];
    const float* b2   = (const float*)d_in[5];
    const float* Wfc  = (const float*)d_in[6];
    const float* bfc  = (const float*)d_in[7];
    float* out = (float*)d_out;

    int E = in_sizes[1] / 2;

    // per-block contiguous dst chunk, staged in dynamic smem
    int chunkN = (((E + GRID - 1) / GRID) + 3) & ~3;
    size_t smem = (size_t)chunkN * 4 + (size_t)NWORDS * 4 + 16;
    bool ok = (E % 4 == 0) && ((chunkN >> 2) <= 6 * TPB) && (smem <= 200 * 1024);
    if (!ok) {
        chunkN = 0;
        smem = (size_t)NWORDS * 4 + 16;
    }
    cudaFuncSetAttribute(gcn_fused_kernel,
                         cudaFuncAttributeMaxDynamicSharedMemorySize, (int)smem);

    gcn_fused_kernel<<<GRID, TPB, smem>>>(eidx, x, W1, b1, W2, b2, Wfc, bfc,
                                          out, E, chunkN);
}

// round 15
// speedup vs baseline: 1.1343x; 1.0105x over previous
#include <cuda_runtime.h>
#include <cuda_bf16.h>
#include <cstdint>
#include <cstddef>

#define NNODES 100000
#define NLAST  (NNODES - 1)
#define NWORDS 3125            // ceil(100000/32)
#define CAP1   4096
#define CAP2   32768
#define GRID   148
#define TPB    1024
#define NTHREADS (GRID * TPB)
#define LOCAL_PAIRS 8

// ---- scratch (device globals; zero at load; cleaned at kernel end) --------
__device__ int           g_deg[NNODES];
__device__ float         g_s[NNODES];
__device__ int           g_s1[CAP1];
__device__ int2          g_pair[CAP2];
__device__ int           g_count1;
__device__ int           g_count2;
__device__ unsigned int  g_cnt[3];     // per-barrier arrival counters

// ---- fire-and-forget grid barrier: REDG arrive + backoff poll -------------
__device__ __forceinline__ void barrier_arrive_wait(int idx) {
    __syncthreads();
    if (threadIdx.x == 0) {
        __threadfence();
        asm volatile("red.relaxed.gpu.global.add.u32 [%0], 1;"
                     :: "l"(g_cnt + idx) : "memory");
        // backoff poll: keeps the LTS queue clear so the releasing
        // arrival isn't stuck behind 148 streaming poll reads
        while (((volatile unsigned int*)g_cnt)[idx] < GRID) {
            __nanosleep(64);
        }
        __threadfence();
    }
    __syncthreads();
}

#define BM_TEST(bm, v)  (((bm)[(v) >> 5] >> ((v) & 31)) & 1u)

// ---------------------------------------------------------------------------
__global__ void __launch_bounds__(TPB, 1)
gcn_fused_kernel(const void* __restrict__ eidx,
                 const float* __restrict__ x,
                 const float* __restrict__ W1, const float* __restrict__ b1,
                 const float* __restrict__ W2, const float* __restrict__ b2,
                 const float* __restrict__ Wfc, const float* __restrict__ bfc,
                 float* __restrict__ out, int E, int chunkN) {
    const int tid = blockIdx.x * TPB + threadIdx.x;

    extern __shared__ unsigned char dynsmem[];
    int*          s_chunk = (int*)dynsmem;
    unsigned int* s_bm    = (unsigned int*)(dynsmem + (size_t)chunkN * 4);

    __shared__ int sh_mode;
    __shared__ int sh_last;

    // per-block dtype detect (same 256B everywhere; L2 broadcast)
    if (threadIdx.x == 0) {
        const unsigned int* w = (const unsigned int*)eidx;
        int all0 = 1;
        #pragma unroll
        for (int i = 0; i < 32; i++)
            if (w[2 * i + 1] != 0u) all0 = 0;
        sh_mode = all0;
        sh_last = 0;
    }
    for (int wdx = threadIdx.x; wdx < NWORDS; wdx += TPB) s_bm[wdx] = 0u;
    __syncthreads();
    const int mode = sh_mode;

    const int* __restrict__ srcp32 = (const int*)eidx;
    const int* __restrict__ dstp32 = srcp32 + E;

    const bool fast = (!mode) && (chunkN > 0) &&
                      (((unsigned long long)(size_t)dstp32 & 15ull) == 0ull);

    const int base = blockIdx.x * chunkN;
    int myN = E - base; if (myN > chunkN) myN = chunkN; if (myN < 0) myN = 0;
    const int nv4 = myN >> 2;                    // myN is a multiple of 4
    const int4* __restrict__ gdv = (const int4*)(dstp32 + base);
    int4* sc4 = (int4*)s_chunk;

    // ================= P1: stage chunk via registers + test dst == N-1 =====
    if (fast) {
        int4 v[6]; int ii[6];
        #pragma unroll
        for (int k = 0; k < 6; k++) {
            ii[k] = threadIdx.x + k * TPB;
            if (ii[k] < nv4) v[k] = gdv[ii[k]];
        }
        // all blocks prefetch a disjoint slice of x into L2 for the tail
        {
            int lines = (NNODES + 31) / 32;                 // 128B lines
            int per_blk = (lines + GRID - 1) / GRID;
            int l0 = blockIdx.x * per_blk;
            for (int l = l0 + threadIdx.x; l < l0 + per_blk && l < lines; l += TPB)
                asm volatile("prefetch.global.L2 [%0];" :: "l"(x + l * 32));
        }
        #pragma unroll
        for (int k = 0; k < 6; k++) {
            if (ii[k] < nv4) {
                sc4[ii[k]] = v[k];
                int gi = base + 4 * ii[k];
                if (v[k].x == NLAST) { int p = atomicAdd(&g_count1, 1); if (p < CAP1) g_s1[p] = srcp32[gi + 0]; }
                if (v[k].y == NLAST) { int p = atomicAdd(&g_count1, 1); if (p < CAP1) g_s1[p] = srcp32[gi + 1]; }
                if (v[k].z == NLAST) { int p = atomicAdd(&g_count1, 1); if (p < CAP1) g_s1[p] = srcp32[gi + 2]; }
                if (v[k].w == NLAST) { int p = atomicAdd(&g_count1, 1); if (p < CAP1) g_s1[p] = srcp32[gi + 3]; }
            }
        }
    } else if (mode) {
        const long long* __restrict__ srcp = (const long long*)eidx;
        const long long* __restrict__ dstp = srcp + E;
        for (int e = tid; e < E; e += NTHREADS) {
            if ((int)dstp[e] == NLAST) { int p = atomicAdd(&g_count1, 1); if (p < CAP1) g_s1[p] = (int)srcp[e]; }
        }
    } else {
        for (int e = tid; e < E; e += NTHREADS) {
            if (dstp32[e] == NLAST) { int p = atomicAdd(&g_count1, 1); if (p < CAP1) g_s1[p] = srcp32[e]; }
        }
    }
    barrier_arrive_wait(0);   // barrier #1

    // build needed bitmask per-block in smem from g_s1
    {
        int c1 = g_count1; if (c1 > CAP1) c1 = CAP1;
        for (int k = threadIdx.x; k < c1; k += TPB) {
            int u = g_s1[k];
            atomicOr(&s_bm[u >> 5], 1u << (u & 31));
        }
        if (threadIdx.x == 0) atomicOr(&s_bm[NLAST >> 5], 1u << (NLAST & 31));
    }
    __syncthreads();

    // ================= P3: scan (smem) — edges into needed set =============
    int   lp_n = 0;
    int   lp_src[LOCAL_PAIRS];
    if (fast) {
        for (int j = threadIdx.x; j < nv4; j += TPB) {
            int4 d4 = sc4[j];
            int gi = base + 4 * j;
            if (BM_TEST(s_bm, d4.x)) { int s = srcp32[gi + 0]; int p = atomicAdd(&g_count2, 1); if (p < CAP2) g_pair[p] = make_int2(s, d4.x); if (lp_n < LOCAL_PAIRS) lp_src[lp_n++] = s; }
            if (BM_TEST(s_bm, d4.y)) { int s = srcp32[gi + 1]; int p = atomicAdd(&g_count2, 1); if (p < CAP2) g_pair[p] = make_int2(s, d4.y); if (lp_n < LOCAL_PAIRS) lp_src[lp_n++] = s; }
            if (BM_TEST(s_bm, d4.z)) { int s = srcp32[gi + 2]; int p = atomicAdd(&g_count2, 1); if (p < CAP2) g_pair[p] = make_int2(s, d4.z); if (lp_n < LOCAL_PAIRS) lp_src[lp_n++] = s; }
            if (BM_TEST(s_bm, d4.w)) { int s = srcp32[gi + 3]; int p = atomicAdd(&g_count2, 1); if (p < CAP2) g_pair[p] = make_int2(s, d4.w); if (lp_n < LOCAL_PAIRS) lp_src[lp_n++] = s; }
        }
    } else if (mode) {
        const long long* __restrict__ srcp = (const long long*)eidx;
        const long long* __restrict__ dstp = srcp + E;
        for (int e = tid; e < E; e += NTHREADS) {
            int d = (int)dstp[e];
            if (BM_TEST(s_bm, d)) { int s = (int)srcp[e]; int p = atomicAdd(&g_count2, 1); if (p < CAP2) g_pair[p] = make_int2(s, d); if (lp_n < LOCAL_PAIRS) lp_src[lp_n++] = s; }
        }
    } else {
        for (int e = tid; e < E; e += NTHREADS) {
            int d = dstp32[e];
            if (BM_TEST(s_bm, d)) { int s = srcp32[e]; int p = atomicAdd(&g_count2, 1); if (p < CAP2) g_pair[p] = make_int2(s, d); if (lp_n < LOCAL_PAIRS) lp_src[lp_n++] = s; }
        }
    }
    // pre-set this block's OWN pair srcs into its bitmask before the barrier
    for (int k = 0; k < lp_n; k++) {
        int u = lp_src[k];
        atomicOr(&s_bm[u >> 5], 1u << (u & 31));
    }
    barrier_arrive_wait(1);   // barrier #2

    // extend bitmask with ALL pair srcs (idempotent; own srcs already set)
    {
        int c2 = g_count2; if (c2 > CAP2) c2 = CAP2;
        for (int k = threadIdx.x; k < c2; k += TPB) {
            int u = __ldcg(&g_pair[k].x);
            atomicOr(&s_bm[u >> 5], 1u << (u & 31));
        }
    }
    __syncthreads();

    // ================= P4: filtered degree scan (smem) =====================
    if (fast) {
        for (int j = threadIdx.x; j < nv4; j += TPB) {
            int4 d4 = sc4[j];
            if (BM_TEST(s_bm, d4.x)) atomicAdd(&g_deg[d4.x], 1);
            if (BM_TEST(s_bm, d4.y)) atomicAdd(&g_deg[d4.y], 1);
            if (BM_TEST(s_bm, d4.z)) atomicAdd(&g_deg[d4.z], 1);
            if (BM_TEST(s_bm, d4.w)) atomicAdd(&g_deg[d4.w], 1);
        }
    } else if (mode) {
        const long long* __restrict__ dstp = (const long long*)eidx + E;
        for (int e = tid; e < E; e += NTHREADS) {
            int d = (int)dstp[e];
            if (BM_TEST(s_bm, d)) atomicAdd(&g_deg[d], 1);
        }
    } else {
        for (int e = tid; e < E; e += NTHREADS) {
            int d = dstp32[e];
            if (BM_TEST(s_bm, d)) atomicAdd(&g_deg[d], 1);
        }
    }

    // ---- final sync: elect the LAST arriving block to run the tail --------
    __syncthreads();
    if (threadIdx.x == 0) {
        __threadfence();
        unsigned p = atomicAdd(&g_cnt[2], 1u);
        sh_last = (p == GRID - 1);
        if (sh_last) __threadfence();   // acquire all blocks' writes
    }
    __syncthreads();
    if (!sh_last) return;

    // ================= P5+P6+cleanup: last-arriving block only =============
    {
        int c1 = g_count1; if (c1 > CAP1) c1 = CAP1;
        int c2 = g_count2; if (c2 > CAP2) c2 = CAP2;

        // P5: layer-1 aggregation over pairs (x is L2-warm from prefetch)
        for (int k = threadIdx.x; k < c2; k += TPB) {
            int2 pr = g_pair[k];
            float dis = rsqrtf((float)(__ldcg(&g_deg[pr.x]) + 1));
            float did = rsqrtf((float)(__ldcg(&g_deg[pr.y]) + 1));
            atomicAdd(&g_s[pr.y], x[pr.x] * dis * did);
        }
        __syncthreads();
        __threadfence();

        // P6: layer-2 @ node N-1 + fc head (warp 0)
        if (threadIdx.x < 32) {
            int lane = threadIdx.x;
            __shared__ float sW1[16], sb1[16], sW2[128], sb2[8], sWfc[8];
            if (lane < 16) { sW1[lane] = W1[lane]; sb1[lane] = b1[lane]; }
            if (lane < 8)  { sb2[lane] = b2[lane]; sWfc[lane] = Wfc[lane]; }
            for (int k = lane; k < 128; k += 32) sW2[k] = W2[k];
            __syncwarp();

            const float dinvL = rsqrtf((float)(__ldcg(&g_deg[NLAST]) + 1));

            float agg[8];
            #pragma unroll
            for (int j = 0; j < 8; j++) agg[j] = 0.0f;

            // k in [0, c1): real edges into N-1; k == c1: appended self-loop.
            for (int k = lane; k <= c1; k += 32) {
                int u = (k == c1) ? NLAST : g_s1[k];
                float du = rsqrtf((float)(__ldcg(&g_deg[u]) + 1));
                float norm = du * dinvL;
                float su = __ldcg(&g_s[u]) + x[u] * du * du;
                float h1[16];
                #pragma unroll
                for (int j = 0; j < 16; j++)
                    h1[j] = fmaxf(fmaf(su, sW1[j], sb1[j]), 0.0f);
                #pragma unroll
                for (int j = 0; j < 8; j++) {
                    float v = 0.0f;
                    #pragma unroll
                    for (int t = 0; t < 16; t++) v = fmaf(h1[t], sW2[t * 8 + j], v);
                    agg[j] = fmaf(v, norm, agg[j]);
                }
            }
            #pragma unroll
            for (int off = 16; off > 0; off >>= 1) {
                #pragma unroll
                for (int j = 0; j < 8; j++)
                    agg[j] += __shfl_down_sync(0xffffffff, agg[j], off);
            }
            if (lane == 0) {
                float o = bfc[0];
                #pragma unroll
                for (int j = 0; j < 8; j++) {
                    float h2 = fmaxf(agg[j] + sb2[j], 0.0f);
                    o = fmaf(h2, sWfc[j], o);
                }
                out[0] = o;
            }
        }
        __syncthreads();

        // cleanup: zero all touched scratch for the next replay
        for (int k = threadIdx.x; k < c1; k += TPB) {
            int u = g_s1[k];
            g_deg[u] = 0; g_s[u] = 0.0f;
        }
        for (int k = threadIdx.x; k < c2; k += TPB) {
            int2 pr = g_pair[k];
            g_deg[pr.x] = 0; g_s[pr.x] = 0.0f;
            g_deg[pr.y] = 0; g_s[pr.y] = 0.0f;
        }
        if (threadIdx.x == 0) {
            g_deg[NLAST] = 0; g_s[NLAST] = 0.0f;
            g_count1 = 0; g_count2 = 0;
            g_cnt[0] = 0u; g_cnt[1] = 0u; g_cnt[2] = 0u;
        }
    }
}

// ---------------------------------------------------------------------------
extern "C" void kernel_launch(void* const* d_in, const int* in_sizes, int n_in,
                              void* d_out, int out_size) {
    const float* x    = (const float*)d_in[0];
    const void*  eidx = d_in[1];
    const float* W1   = (const float*)d_in[2];
    const float* b1   = (const float*)d_in[3];
    const float* W2   = (const float*)d_in[4];
    const float* b2   = (const float*)d_in[5];
    const float* Wfc  = (const float*)d_in[6];
    const float* bfc  = (const float*)d_in[7];
    float* out = (float*)d_out;

    int E = in_sizes[1] / 2;

    // per-block contiguous dst chunk, staged in dynamic smem
    int chunkN = (((E + GRID - 1) / GRID) + 3) & ~3;
    size_t smem = (size_t)chunkN * 4 + (size_t)NWORDS * 4 + 16;
    bool ok = (E % 4 == 0) && ((chunkN >> 2) <= 6 * TPB) && (smem <= 200 * 1024);
    if (!ok) {
        chunkN = 0;
        smem = (size_t)NWORDS * 4 + 16;
    }
    cudaFuncSetAttribute(gcn_fused_kernel,
                         cudaFuncAttributeMaxDynamicSharedMemorySize, (int)smem);

    gcn_fused_kernel<<<GRID, TPB, smem>>>(eidx, x, W1, b1, W2, b2, Wfc, bfc,
                                          out, E, chunkN);
}